// round 3
// baseline (speedup 1.0000x reference)
#include <cuda_runtime.h>
#include <cstdint>

// ============================================================================
// KLinear: y = x @ W + bias,  W = (kron(L0,R0)+kron(L1,R1)+kron(L2,R2))/3
//
// Factorized (no W materialization):
//   T[m,a,d] = sum_c x[m, a*C+c] * R[c,d]
//   y[m, b*D+d] += sum_a L[a,b] * T[m,a,d]
// Total ~3.0e10 MACs vs 2.75e11 dense. Fully fused in one kernel:
// CTA owns 4 rows of x; y tile accumulated in SMEM across all 3 factors.
// Base-ISA only (no tcgen05 — harness targets sm_103, not sm_103a).
// ============================================================================

static constexpr int MT      = 4;     // rows per CTA
static constexpr int THREADS = 256;
static constexpr int NF      = 4096;  // IN = OUT = 4096

// SMEM layout (floats)
static constexpr int OFF_Y  = 0;            // [4][4096]        = 16384
static constexpr int OFF_LR = 16384;        // L then R         <= 17408
static constexpr int OFF_T  = 33792;        // [4][8][<=128]    = 4096
static constexpr int OFF_X  = 37888;        // [4][8*C<=1024]   = 4096
static constexpr int SMEM_FLOATS = 41984;
static constexpr int SMEM_BYTES  = SMEM_FLOATS * 4;   // 167936

template<int A, int B, int C, int D>
__device__ __forceinline__ void process_factor(
    const float* __restrict__ Lg, const float* __restrict__ Rg,
    const float* __restrict__ x,
    float* __restrict__ ysm, float* __restrict__ LRsm,
    float* __restrict__ Tsm, float* __restrict__ xsm,
    int m0, int tid)
{
    constexpr int ABLK = 8;
    constexpr int NBLK = A / ABLK;        // 8 / 4 / 16
    constexpr int DJ   = D / 32;          // stage1 d's per thread (2/4/1)
    constexpr int D4   = D / 4;           // stage2 d stride
    constexpr int XV   = ABLK * C / 4;    // float4 per row in x slab

    float* Lsm = LRsm;
    float* Rsm = LRsm + A * B;

    // Order previous factor's stage2/flush before overwriting Lsm/Rsm.
    __syncthreads();
    for (int i = tid; i < A * B; i += THREADS) Lsm[i] = Lg[i] * (1.0f / 3.0f);
    for (int i = tid; i < C * D; i += THREADS) Rsm[i] = Rg[i];

    // stage2 thread tile: (4 b) x (4 d, strided by D/4) for each of 4 m
    const int bq  = tid / D4;             // 0 .. B/4-1
    const int dq  = tid - bq * D4;        // 0 .. D/4-1
    // stage1 mapping: warp -> ar, lane -> d base
    const int ar1 = tid >> 5;             // 0..7
    const int dl  = tid & 31;

    float yacc[MT][4][4];
    #pragma unroll
    for (int m = 0; m < MT; m++)
        #pragma unroll
        for (int i = 0; i < 4; i++)
            #pragma unroll
            for (int j = 0; j < 4; j++)
                yacc[m][i][j] = 0.0f;

    for (int ab = 0; ab < NBLK; ab++) {
        // protect xsm/Tsm reuse (also orders L/R load on first iter)
        __syncthreads();

        // ---- load x slab: x[m0+m][ab*ABLK*C .. +ABLK*C) -> xsm ----
        {
            float4* xs4 = reinterpret_cast<float4*>(xsm);
            const float4* xg4 = reinterpret_cast<const float4*>(x);
            const int gbase = ab * (ABLK * C) / 4;
            #pragma unroll
            for (int i = tid; i < MT * XV; i += THREADS) {
                int m = i / XV, o = i - m * XV;
                xs4[i] = xg4[(size_t)(m0 + m) * (NF / 4) + gbase + o];
            }
        }
        __syncthreads();

        // ---- stage 1: T[m][ar][d] = sum_c xsm[m][ar*C+c] * R[c][d] ----
        {
            float acc[MT][DJ];
            #pragma unroll
            for (int m = 0; m < MT; m++)
                #pragma unroll
                for (int j = 0; j < DJ; j++) acc[m][j] = 0.0f;

            #pragma unroll 4
            for (int c = 0; c < C; c++) {
                float rv[DJ];
                #pragma unroll
                for (int j = 0; j < DJ; j++) rv[j] = Rsm[c * D + dl + j * 32];
                #pragma unroll
                for (int m = 0; m < MT; m++) {
                    float xv = xsm[m * (ABLK * C) + ar1 * C + c];
                    #pragma unroll
                    for (int j = 0; j < DJ; j++)
                        acc[m][j] = fmaf(xv, rv[j], acc[m][j]);
                }
            }
            #pragma unroll
            for (int m = 0; m < MT; m++)
                #pragma unroll
                for (int j = 0; j < DJ; j++)
                    Tsm[(m * ABLK + ar1) * D + dl + j * 32] = acc[m][j];
        }
        __syncthreads();

        // ---- stage 2: yacc[m][i][j] += L[a][bq*4+i] * T[m][ar][dq + j*D4] ----
        #pragma unroll
        for (int ar = 0; ar < ABLK; ar++) {
            float lv[4];
            #pragma unroll
            for (int i = 0; i < 4; i++)
                lv[i] = Lsm[(ab * ABLK + ar) * B + bq * 4 + i];
            #pragma unroll
            for (int m = 0; m < MT; m++) {
                float tv[4];
                #pragma unroll
                for (int j = 0; j < 4; j++)
                    tv[j] = Tsm[(m * ABLK + ar) * D + dq + j * D4];
                #pragma unroll
                for (int i = 0; i < 4; i++)
                    #pragma unroll
                    for (int j = 0; j < 4; j++)
                        yacc[m][i][j] = fmaf(lv[i], tv[j], yacc[m][i][j]);
            }
        }
    }

    // ---- flush register tile into y smem (per-thread-disjoint addresses) ----
    #pragma unroll
    for (int m = 0; m < MT; m++)
        #pragma unroll
        for (int i = 0; i < 4; i++)
            #pragma unroll
            for (int j = 0; j < 4; j++)
                ysm[m * NF + (bq * 4 + i) * D + dq + j * D4] += yacc[m][i][j];
}

__global__ __launch_bounds__(THREADS, 1) void klinear_kernel(
    const float* __restrict__ x,
    const float* __restrict__ L0, const float* __restrict__ R0,
    const float* __restrict__ L1, const float* __restrict__ R1,
    const float* __restrict__ L2, const float* __restrict__ R2,
    const float* __restrict__ bias,
    float* __restrict__ out)
{
    extern __shared__ float smem[];
    float* ysm  = smem + OFF_Y;
    float* LRsm = smem + OFF_LR;
    float* Tsm  = smem + OFF_T;
    float* xsm  = smem + OFF_X;

    const int tid = threadIdx.x;
    const int m0  = blockIdx.x * MT;

    // init y accumulator with bias (1/3 is folded into L)
    for (int i = tid; i < MT * NF; i += THREADS)
        ysm[i] = bias[i & (NF - 1)];

    process_factor< 64,  64,  64,  64>(L0, R0, x, ysm, LRsm, Tsm, xsm, m0, tid);
    process_factor< 32,  32, 128, 128>(L1, R1, x, ysm, LRsm, Tsm, xsm, m0, tid);
    process_factor<128, 128,  32,  32>(L2, R2, x, ysm, LRsm, Tsm, xsm, m0, tid);

    __syncthreads();
    // write out (coalesced float4)
    const float4* y4 = reinterpret_cast<const float4*>(ysm);
    #pragma unroll
    for (int i = tid; i < MT * NF / 4; i += THREADS) {
        int m = i / (NF / 4), o = i - m * (NF / 4);
        reinterpret_cast<float4*>(out + (size_t)(m0 + m) * NF)[o] = y4[i];
    }
}

extern "C" void kernel_launch(void* const* d_in, const int* in_sizes, int n_in,
                              void* d_out, int out_size)
{
    const float* x    = (const float*)d_in[0];
    const float* L0   = (const float*)d_in[1];
    const float* R0   = (const float*)d_in[2];
    const float* L1   = (const float*)d_in[3];
    const float* R1   = (const float*)d_in[4];
    const float* L2   = (const float*)d_in[5];
    const float* R2   = (const float*)d_in[6];
    const float* bias = (const float*)d_in[7];
    float* out = (float*)d_out;

    static bool attr_set = false;
    if (!attr_set) {
        cudaFuncSetAttribute(klinear_kernel,
                             cudaFuncAttributeMaxDynamicSharedMemorySize, SMEM_BYTES);
        attr_set = true;
    }

    const int M = 16384;
    klinear_kernel<<<M / MT, THREADS, SMEM_BYTES>>>(
        x, L0, R0, L1, R1, L2, R2, bias, out);
}

// round 4
// speedup vs baseline: 1.5252x; 1.5252x over previous
#include <cuda_runtime.h>
#include <cstdint>

// ============================================================================
// KLinear: y = x @ W + bias,  W = (kron(L0,R0)+kron(L1,R1)+kron(L2,R2))/3
// Factorized: T[m,a,d] = sum_c x[m,aC+c] R[c,d];  y[m,bD+d] += sum_a L[a,b] T[m,a,d]
// y kept in registers across all factors: thread owns n = tid*4 + 1024*g + j.
// Since D | 1024, d = (tid*4) % D is identical for all 4 groups -> one float4
// T load feeds 16 FMAs. L streamed in 8-row slabs. smem ~100KB -> 2 CTAs/SM.
// ============================================================================

static constexpr int MT      = 4;
static constexpr int THREADS = 256;
static constexpr int NF      = 4096;

// SMEM layout (floats)
static constexpr int OFF_R = 0;        // [C][D]      <= 16384
static constexpr int OFF_L = 16384;    // [8][B]      <= 1024
static constexpr int OFF_T = 17408;    // [MT][8][D]  <= 4096
static constexpr int OFF_X = 21504;    // [MT][8*C]   <= 4096
static constexpr int SMEM_FLOATS = 25600;
static constexpr int SMEM_BYTES  = SMEM_FLOATS * 4;   // 102400

template<int A, int B, int C, int D>
__device__ __forceinline__ void process_factor(
    const float* __restrict__ Lg, const float* __restrict__ Rg,
    const float* __restrict__ x, float* __restrict__ smem,
    float (&yreg)[MT][4][4], int m0, int tid)
{
    constexpr int ABLK = 8;
    constexpr int NBLK = A / ABLK;
    constexpr int DJ   = D / 32;             // 2 / 4 / 1
    constexpr int CU   = (DJ == 4) ? 2 : 4;  // c-unroll (bound register use)
    constexpr int BG   = 1024 / D;           // b stride between groups

    float* Rsm = smem + OFF_R;
    float* Lsm = smem + OFF_L;
    float* Tsm = smem + OFF_T;
    float* xsm = smem + OFF_X;

    const int ar1 = tid >> 5;                // stage1: warp -> a-row
    const int dl  = tid & 31;                // stage1: lane -> d block
    const int d0  = (tid * 4) & (D - 1);     // stage2: d base (same all groups)
    const int b0  = (tid * 4) / D;           // stage2: b for group 0

    // Load R [C][D]. Disjoint from T/L/x regions read by the previous factor's
    // tail; the first in-loop __syncthreads orders it before use.
    for (int i = tid; i < C * D; i += THREADS) Rsm[i] = Rg[i];

    for (int ab = 0; ab < NBLK; ab++) {
        __syncthreads();   // protects T/L/x reuse (and R on first iter)

        // ---- x slab: rows m0..m0+3, cols [ab*8C, ab*8C + 8C) ----
        {
            constexpr int XV = ABLK * C / 4;
            const float4* xg4 = reinterpret_cast<const float4*>(x);
            float4* xs4 = reinterpret_cast<float4*>(xsm);
            #pragma unroll
            for (int i = tid; i < MT * XV; i += THREADS) {
                int m = i / XV, o = i - m * XV;
                xs4[i] = xg4[(size_t)(m0 + m) * (NF / 4) + ab * XV + o];
            }
        }
        // ---- L slab: rows a = ab*8 .. ab*8+7, fold 1/3 ----
        #pragma unroll
        for (int i = tid; i < ABLK * B; i += THREADS)
            Lsm[i] = Lg[ab * ABLK * B + i] * (1.0f / 3.0f);
        __syncthreads();

        // ---- stage 1: T[m][ar1][dl*DJ+j] = sum_c x[m][ar1*C+c] * R[c][...] ----
        {
            float acc[MT][DJ];
            #pragma unroll
            for (int m = 0; m < MT; m++)
                #pragma unroll
                for (int j = 0; j < DJ; j++) acc[m][j] = 0.0f;

            #pragma unroll 2
            for (int c = 0; c < C; c += CU) {
                float rv[CU][DJ];
                #pragma unroll
                for (int cc = 0; cc < CU; cc++) {
                    if constexpr (DJ == 4) {
                        float4 t = *(const float4*)&Rsm[(c + cc) * D + dl * 4];
                        rv[cc][0] = t.x; rv[cc][1] = t.y; rv[cc][2] = t.z; rv[cc][3] = t.w;
                    } else if constexpr (DJ == 2) {
                        float2 t = *(const float2*)&Rsm[(c + cc) * D + dl * 2];
                        rv[cc][0] = t.x; rv[cc][1] = t.y;
                    } else {
                        rv[cc][0] = Rsm[(c + cc) * D + dl];
                    }
                }
                #pragma unroll
                for (int m = 0; m < MT; m++) {
                    float xa[CU];
                    if constexpr (CU == 4) {
                        float4 t = *(const float4*)&xsm[m * (ABLK * C) + ar1 * C + c];
                        xa[0] = t.x; xa[1] = t.y; xa[2] = t.z; xa[3] = t.w;
                    } else {
                        float2 t = *(const float2*)&xsm[m * (ABLK * C) + ar1 * C + c];
                        xa[0] = t.x; xa[1] = t.y;
                    }
                    #pragma unroll
                    for (int cc = 0; cc < CU; cc++)
                        #pragma unroll
                        for (int j = 0; j < DJ; j++)
                            acc[m][j] = fmaf(xa[cc], rv[cc][j], acc[m][j]);
                }
            }
            #pragma unroll
            for (int m = 0; m < MT; m++) {
                if constexpr (DJ == 4) {
                    *(float4*)&Tsm[(m * ABLK + ar1) * D + dl * 4] =
                        make_float4(acc[m][0], acc[m][1], acc[m][2], acc[m][3]);
                } else if constexpr (DJ == 2) {
                    *(float2*)&Tsm[(m * ABLK + ar1) * D + dl * 2] =
                        make_float2(acc[m][0], acc[m][1]);
                } else {
                    Tsm[(m * ABLK + ar1) * D + dl] = acc[m][0];
                }
            }
        }
        __syncthreads();

        // ---- stage 2: yreg[m][g][j] += L[a][b0+g*BG] * T[m][ar][d0+j] ----
        #pragma unroll 2
        for (int ar = 0; ar < ABLK; ar++) {
            float lv[4];
            #pragma unroll
            for (int g = 0; g < 4; g++)
                lv[g] = Lsm[ar * B + b0 + g * BG];
            #pragma unroll
            for (int m = 0; m < MT; m++) {
                float4 tv = *(const float4*)&Tsm[(m * ABLK + ar) * D + d0];
                float ta[4] = {tv.x, tv.y, tv.z, tv.w};
                #pragma unroll
                for (int g = 0; g < 4; g++)
                    #pragma unroll
                    for (int j = 0; j < 4; j++)
                        yreg[m][g][j] = fmaf(lv[g], ta[j], yreg[m][g][j]);
            }
        }
    }
}

__global__ __launch_bounds__(THREADS, 2) void klinear_kernel(
    const float* __restrict__ x,
    const float* __restrict__ L0, const float* __restrict__ R0,
    const float* __restrict__ L1, const float* __restrict__ R1,
    const float* __restrict__ L2, const float* __restrict__ R2,
    const float* __restrict__ bias,
    float* __restrict__ out)
{
    extern __shared__ float smem[];
    const int tid = threadIdx.x;
    const int m0  = blockIdx.x * MT;

    float yreg[MT][4][4];
    #pragma unroll
    for (int m = 0; m < MT; m++)
        #pragma unroll
        for (int g = 0; g < 4; g++)
            #pragma unroll
            for (int j = 0; j < 4; j++)
                yreg[m][g][j] = 0.0f;

    process_factor< 64,  64,  64,  64>(L0, R0, x, smem, yreg, m0, tid);
    process_factor< 32,  32, 128, 128>(L1, R1, x, smem, yreg, m0, tid);
    process_factor<128, 128,  32,  32>(L2, R2, x, smem, yreg, m0, tid);

    // epilogue: add bias, write float4 (n = tid*4 + 1024*g + j)
    #pragma unroll
    for (int g = 0; g < 4; g++) {
        float4 bv = *(const float4*)&bias[tid * 4 + 1024 * g];
        #pragma unroll
        for (int m = 0; m < MT; m++) {
            float4 v;
            v.x = yreg[m][g][0] + bv.x;
            v.y = yreg[m][g][1] + bv.y;
            v.z = yreg[m][g][2] + bv.z;
            v.w = yreg[m][g][3] + bv.w;
            *(float4*)&out[(size_t)(m0 + m) * NF + tid * 4 + 1024 * g] = v;
        }
    }
}

extern "C" void kernel_launch(void* const* d_in, const int* in_sizes, int n_in,
                              void* d_out, int out_size)
{
    const float* x    = (const float*)d_in[0];
    const float* L0   = (const float*)d_in[1];
    const float* R0   = (const float*)d_in[2];
    const float* L1   = (const float*)d_in[3];
    const float* R1   = (const float*)d_in[4];
    const float* L2   = (const float*)d_in[5];
    const float* R2   = (const float*)d_in[6];
    const float* bias = (const float*)d_in[7];
    float* out = (float*)d_out;

    static bool attr_set = false;
    if (!attr_set) {
        cudaFuncSetAttribute(klinear_kernel,
                             cudaFuncAttributeMaxDynamicSharedMemorySize, SMEM_BYTES);
        attr_set = true;
    }

    klinear_kernel<<<16384 / MT, THREADS, SMEM_BYTES>>>(
        x, L0, R0, L1, R1, L2, R2, bias, out);
}

// round 5
// speedup vs baseline: 1.5306x; 1.0035x over previous
#include <cuda_runtime.h>
#include <cstdint>

// ============================================================================
// KLinear: y = x @ W + bias,  W = (kron(L0,R0)+kron(L1,R1)+kron(L2,R2))/3
// Factorized: T[m,a,d] = sum_c x[m,aC+c] R[c,d];  y[m,bD+d] += sum_a L[a,b] T[m,a,d]
// y in registers (thread owns n = tid*4 + 1024*g + j; D | 1024 -> shared d0).
// This round: fma.rn.f32x2 packed math (halve FFMA instrs), 2 a-rows/warp with
// 16-lane halves + d-split across warp pairs (halve stage-1 R wavefronts),
// padded x slab (kill 2-way broadcast bank conflict).
// ============================================================================

static constexpr int MT      = 4;
static constexpr int THREADS = 256;
static constexpr int NF      = 4096;

typedef unsigned long long u64t;

#define FMA2(acc, a, b) \
    asm("fma.rn.f32x2 %0, %1, %2, %0;" : "+l"(acc) : "l"(a), "l"(b))

__device__ __forceinline__ u64t pack2(float lo, float hi) {
    u64t r; asm("mov.b64 %0, {%1, %2};" : "=l"(r) : "f"(lo), "f"(hi)); return r;
}
__device__ __forceinline__ u64t dup2(float v) { return pack2(v, v); }
__device__ __forceinline__ float2 unpack2(u64t p) {
    float lo, hi; asm("mov.b64 {%0, %1}, %2;" : "=f"(lo), "=f"(hi) : "l"(p));
    return make_float2(lo, hi);
}

// SMEM layout (floats)
static constexpr int OFF_R = 0;        // [C][D]            <= 16384
static constexpr int OFF_L = 16384;    // [8][B]            <= 1024
static constexpr int OFF_T = 17408;    // [MT][8][D]        <= 4096
static constexpr int OFF_X = 21504;    // [MT][8][(C+4)]    <= 4224
static constexpr int SMEM_FLOATS = 25728;
static constexpr int SMEM_BYTES  = SMEM_FLOATS * 4;   // 102912

template<int A, int B, int C, int D>
__device__ __forceinline__ void process_factor(
    const float* __restrict__ Lg, const float* __restrict__ Rg,
    const float* __restrict__ x, float* __restrict__ smem,
    u64t (&yreg)[MT][4][2], int m0, int tid)
{
    constexpr int ABLK = 8;
    constexpr int NBLK = A / ABLK;
    constexpr int DJ   = D / 32;             // 2 / 4 / 1
    constexpr int CU   = (DJ == 4) ? 2 : 4;  // c-unroll
    constexpr int BG   = 1024 / D;           // b stride between groups
    constexpr int XROW = C + 4;              // padded x row (bank shift)

    float* Rsm = smem + OFF_R;
    float* Lsm = smem + OFF_L;
    float* Tsm = smem + OFF_T;
    float* xsm = smem + OFF_X;

    const int wid    = tid >> 5;
    const int lane   = tid & 31;
    const int lane16 = lane & 15;
    // stage1: warp-pair covers 2 a-rows; warp parity selects d-half
    const int ar1   = (wid >> 1) * 2 + (lane >> 4);       // 0..7
    const int dbase = (wid & 1) * (D / 2) + lane16 * DJ;  // this lane's d base
    // stage2: d0 identical for all 4 groups
    const int d0 = (tid * 4) & (D - 1);
    const int b0 = (tid * 4) / D;

    for (int i = tid; i < C * D; i += THREADS) Rsm[i] = Rg[i];

    for (int ab = 0; ab < NBLK; ab++) {
        __syncthreads();   // protects T/L/x reuse (and R on first iter)

        // ---- x slab (padded rows): x[m0+m][ab*8C + ar*C + c] -> xsm[m][ar][c] ----
        {
            const float4* xg4 = reinterpret_cast<const float4*>(x);
            #pragma unroll
            for (int i = tid; i < MT * ABLK * (C / 4); i += THREADS) {
                int m  = i / (ABLK * C / 4);
                int o  = i - m * (ABLK * C / 4);      // float4 idx within row slab
                int ar = o / (C / 4);
                int c4 = o - ar * (C / 4);
                float4 v = xg4[(size_t)(m0 + m) * (NF / 4) + ab * (ABLK * C / 4) + o];
                *(float4*)&xsm[(m * ABLK + ar) * XROW + c4 * 4] = v;
            }
        }
        // ---- L slab (fold 1/3) ----
        #pragma unroll
        for (int i = tid; i < ABLK * B; i += THREADS)
            Lsm[i] = Lg[ab * ABLK * B + i] * (1.0f / 3.0f);
        __syncthreads();

        // ---- stage 1: T[m][ar1][dbase..+DJ) = sum_c x[m][ar1*C+c] * R[c][..] ----
        if constexpr (DJ >= 2) {
            u64t acc[MT][DJ / 2];
            #pragma unroll
            for (int m = 0; m < MT; m++)
                #pragma unroll
                for (int j = 0; j < DJ / 2; j++) acc[m][j] = 0ull;

            for (int c = 0; c < C; c += CU) {
                u64t rv[CU][DJ / 2];
                #pragma unroll
                for (int cc = 0; cc < CU; cc++) {
                    if constexpr (DJ == 4) {
                        ulonglong2 t = *(const ulonglong2*)&Rsm[(c + cc) * D + dbase];
                        rv[cc][0] = t.x; rv[cc][1] = t.y;
                    } else {
                        rv[cc][0] = *(const u64t*)&Rsm[(c + cc) * D + dbase];
                    }
                }
                #pragma unroll
                for (int m = 0; m < MT; m++) {
                    float xa[CU];
                    if constexpr (CU == 4) {
                        float4 t = *(const float4*)&xsm[(m * ABLK + ar1) * XROW + c];
                        xa[0] = t.x; xa[1] = t.y; xa[2] = t.z; xa[3] = t.w;
                    } else {
                        float2 t = *(const float2*)&xsm[(m * ABLK + ar1) * XROW + c];
                        xa[0] = t.x; xa[1] = t.y;
                    }
                    #pragma unroll
                    for (int cc = 0; cc < CU; cc++) {
                        u64t xd = dup2(xa[cc]);
                        #pragma unroll
                        for (int j = 0; j < DJ / 2; j++)
                            FMA2(acc[m][j], xd, rv[cc][j]);
                    }
                }
            }
            #pragma unroll
            for (int m = 0; m < MT; m++) {
                if constexpr (DJ == 4) {
                    ulonglong2 t; t.x = acc[m][0]; t.y = acc[m][1];
                    *(ulonglong2*)&Tsm[(m * ABLK + ar1) * D + dbase] = t;
                } else {
                    *(u64t*)&Tsm[(m * ABLK + ar1) * D + dbase] = acc[m][0];
                }
            }
        } else {
            // DJ == 1 (D == 32): pair over m instead of d
            u64t acc[MT / 2];
            #pragma unroll
            for (int p = 0; p < MT / 2; p++) acc[p] = 0ull;

            for (int c = 0; c < C; c += CU) {
                float rv[CU];
                #pragma unroll
                for (int cc = 0; cc < CU; cc++)
                    rv[cc] = Rsm[(c + cc) * D + dbase];
                float xa[MT][CU];
                #pragma unroll
                for (int m = 0; m < MT; m++) {
                    float4 t = *(const float4*)&xsm[(m * ABLK + ar1) * XROW + c];
                    xa[m][0] = t.x; xa[m][1] = t.y; xa[m][2] = t.z; xa[m][3] = t.w;
                }
                #pragma unroll
                for (int cc = 0; cc < CU; cc++) {
                    u64t rd = dup2(rv[cc]);
                    #pragma unroll
                    for (int p = 0; p < MT / 2; p++) {
                        u64t xp = pack2(xa[2 * p][cc], xa[2 * p + 1][cc]);
                        FMA2(acc[p], xp, rd);
                    }
                }
            }
            #pragma unroll
            for (int p = 0; p < MT / 2; p++) {
                float2 v = unpack2(acc[p]);
                Tsm[((2 * p)     * ABLK + ar1) * D + dbase] = v.x;
                Tsm[((2 * p + 1) * ABLK + ar1) * D + dbase] = v.y;
            }
        }
        __syncthreads();

        // ---- stage 2: y[m][g][d0+j] += L[a][b0+g*BG] * T[m][ar][d0+j] ----
        #pragma unroll 2
        for (int ar = 0; ar < ABLK; ar++) {
            u64t lp[4];
            #pragma unroll
            for (int g = 0; g < 4; g++)
                lp[g] = dup2(Lsm[ar * B + b0 + g * BG]);
            #pragma unroll
            for (int m = 0; m < MT; m++) {
                ulonglong2 tp = *(const ulonglong2*)&Tsm[(m * ABLK + ar) * D + d0];
                #pragma unroll
                for (int g = 0; g < 4; g++) {
                    FMA2(yreg[m][g][0], lp[g], tp.x);
                    FMA2(yreg[m][g][1], lp[g], tp.y);
                }
            }
        }
    }
}

__global__ __launch_bounds__(THREADS, 2) void klinear_kernel(
    const float* __restrict__ x,
    const float* __restrict__ L0, const float* __restrict__ R0,
    const float* __restrict__ L1, const float* __restrict__ R1,
    const float* __restrict__ L2, const float* __restrict__ R2,
    const float* __restrict__ bias,
    float* __restrict__ out)
{
    extern __shared__ float smem[];
    const int tid = threadIdx.x;
    const int m0  = blockIdx.x * MT;

    u64t yreg[MT][4][2];
    #pragma unroll
    for (int m = 0; m < MT; m++)
        #pragma unroll
        for (int g = 0; g < 4; g++) {
            yreg[m][g][0] = 0ull; yreg[m][g][1] = 0ull;
        }

    process_factor< 64,  64,  64,  64>(L0, R0, x, smem, yreg, m0, tid);
    process_factor< 32,  32, 128, 128>(L1, R1, x, smem, yreg, m0, tid);
    process_factor<128, 128,  32,  32>(L2, R2, x, smem, yreg, m0, tid);

    // epilogue: add bias, write float4 (n = tid*4 + 1024*g + j)
    #pragma unroll
    for (int g = 0; g < 4; g++) {
        float4 bv = *(const float4*)&bias[tid * 4 + 1024 * g];
        #pragma unroll
        for (int m = 0; m < MT; m++) {
            float2 v01 = unpack2(yreg[m][g][0]);
            float2 v23 = unpack2(yreg[m][g][1]);
            float4 v;
            v.x = v01.x + bv.x;
            v.y = v01.y + bv.y;
            v.z = v23.x + bv.z;
            v.w = v23.y + bv.w;
            *(float4*)&out[(size_t)(m0 + m) * NF + tid * 4 + 1024 * g] = v;
        }
    }
}

extern "C" void kernel_launch(void* const* d_in, const int* in_sizes, int n_in,
                              void* d_out, int out_size)
{
    const float* x    = (const float*)d_in[0];
    const float* L0   = (const float*)d_in[1];
    const float* R0   = (const float*)d_in[2];
    const float* L1   = (const float*)d_in[3];
    const float* R1   = (const float*)d_in[4];
    const float* L2   = (const float*)d_in[5];
    const float* R2   = (const float*)d_in[6];
    const float* bias = (const float*)d_in[7];
    float* out = (float*)d_out;

    static bool attr_set = false;
    if (!attr_set) {
        cudaFuncSetAttribute(klinear_kernel,
                             cudaFuncAttributeMaxDynamicSharedMemorySize, SMEM_BYTES);
        attr_set = true;
    }

    klinear_kernel<<<16384 / MT, THREADS, SMEM_BYTES>>>(
        x, L0, R0, L1, R1, L2, R2, bias, out);
}

// round 7
// speedup vs baseline: 2.8577x; 1.8671x over previous
#include <cuda_runtime.h>
#include <cstdint>

// ============================================================================
// KLinear: y = x @ W + bias,  W = (kron(L0,R0)+kron(L1,R1)+kron(L2,R2))/3
// Factorized two-stage GEMMs on legacy tensor cores (mma.sync m16n8k8 tf32,
// base ISA — tcgen05 unavailable: harness targets sm_103, not sm_103a).
//   GEMM1: T[(m,a), d] = sum_c x[m, a*C+c] * R[c,d]      (M=4A, N=D, K=C)
//   GEMM2: y[m][b*D+d] += sum_a (L[a,b]/3) * T[(m,a), d]  (per m: M=B, N=D, K=A)
// CTA = 4 rows of x, 512 threads / 16 warps, 8 m16n8 tiles per warp per GEMM.
// y accumulated in swizzled smem across factors; bias added at epilogue.
// R6 bug fixed: y row stride must cover n + 2*(n>>5) -> YS = 4352 (was 4224).
// ============================================================================

static constexpr int THREADS = 512;
static constexpr int MT = 4;
static constexpr int NF = 4096;

// SMEM layout (float indices)
static constexpr int YS    = 4352;            // y row stride: 4096 + 2*(4096/32)
static constexpr int OFF_Y = 0;               // 4 * 4352          = 17408
static constexpr int OFF_T = 17408;           // up to 512*40      = 20480
static constexpr int OFF_X = 37888;           // up to 512*20      = 10240 (aliased by LT)
static constexpr int OFF_R = 48128;           // up to 16*136      = 2176
static constexpr int SMEM_FLOATS = 50304;
static constexpr int SMEM_BYTES  = SMEM_FLOATS * 4;   // 201216 B

__device__ __forceinline__ uint32_t f2tf(float f) {
    uint32_t r; asm("cvt.rna.tf32.f32 %0, %1;" : "=r"(r) : "f"(f)); return r;
}

__device__ __forceinline__ void mma8(float* c, const uint32_t* a, const uint32_t* b) {
    asm volatile(
        "mma.sync.aligned.m16n8k8.row.col.f32.tf32.tf32.f32 "
        "{%0,%1,%2,%3}, {%4,%5,%6,%7}, {%8,%9}, {%0,%1,%2,%3};"
        : "+f"(c[0]), "+f"(c[1]), "+f"(c[2]), "+f"(c[3])
        : "r"(a[0]), "r"(a[1]), "r"(a[2]), "r"(a[3]), "r"(b[0]), "r"(b[1]));
}

template<int A, int B, int C, int D>
__device__ __forceinline__ void factor(
    const float* __restrict__ x, const float* __restrict__ Lg,
    const float* __restrict__ Rg, float* __restrict__ smem, int m0, int tid)
{
    constexpr int DP  = D + 8;          // padded row stride (R, T): conflict-free frags
    constexpr int XS  = 20;             // x chunk row stride (16 + 4)
    constexpr int LTS = 36;             // LT chunk row stride (32 + 4)
    constexpr int NC1 = C / 16;         // K chunks, stage 1
    constexpr int NC2 = A / 32;         // K chunks, stage 2
    constexpr int TC1 = D / 8;          // GEMM1 tile grid: (4A/16) x (D/8) = 128
    constexpr int WC1 = TC1 / 4;        // warp grid cols (warp block = 2x4 tiles)
    constexpr int TC2 = D / 8;          // GEMM2 per-m grid: (B/16) x (D/8) = 32
    constexpr int WC2 = (TC2 >= 4) ? ((TC2 / 4 <= 4) ? TC2 / 4 : 4) : 1;

    float*    ys  = smem + OFF_Y;
    uint32_t* ts  = (uint32_t*)(smem + OFF_T);
    uint32_t* xs  = (uint32_t*)(smem + OFF_X);
    uint32_t* rs  = (uint32_t*)(smem + OFF_R);
    uint32_t* lts = (uint32_t*)(smem + OFF_X);   // alias (x chunk dead in stage 2)

    const int w    = tid >> 5;
    const int lane = tid & 31;
    const int gid  = lane >> 2;     // groupID
    const int tig  = lane & 3;      // thread-in-group

    // ================= GEMM1 =================
    const int wr1 = w / WC1, wc1 = w % WC1;
    float accT[2][4][4];
    #pragma unroll
    for (int i = 0; i < 2; i++)
        #pragma unroll
        for (int j = 0; j < 4; j++)
            #pragma unroll
            for (int q = 0; q < 4; q++) accT[i][j][q] = 0.0f;

    for (int ck = 0; ck < NC1; ck++) {
        __syncthreads();   // prev chunk consumed / prev factor fully done

        // ---- x chunk: [4A rows][16 c], tf32, stride 20 ----
        #pragma unroll
        for (int i4 = tid; i4 < 4 * A * 4; i4 += THREADS) {
            int r = i4 >> 2, c4 = i4 & 3;
            int m = r / A, a = r % A;
            float4 v = *(const float4*)&x[(size_t)(m0 + m) * NF + a * C + ck * 16 + c4 * 4];
            uint4 u = make_uint4(f2tf(v.x), f2tf(v.y), f2tf(v.z), f2tf(v.w));
            *(uint4*)&xs[r * XS + c4 * 4] = u;
        }
        // ---- R chunk: [16 c][D], tf32, stride DP ----
        #pragma unroll
        for (int i4 = tid; i4 < 16 * (D / 4); i4 += THREADS) {
            int k = i4 / (D / 4), d4 = i4 % (D / 4);
            float4 v = *(const float4*)&Rg[(ck * 16 + k) * D + d4 * 4];
            uint4 u = make_uint4(f2tf(v.x), f2tf(v.y), f2tf(v.z), f2tf(v.w));
            *(uint4*)&rs[k * DP + d4 * 4] = u;
        }
        __syncthreads();

        #pragma unroll
        for (int kt = 0; kt < 2; kt++) {
            uint32_t af[2][4], bf[4][2];
            #pragma unroll
            for (int i = 0; i < 2; i++) {
                int r0 = (wr1 * 2 + i) * 16 + gid;
                af[i][0] = xs[r0 * XS + kt * 8 + tig];
                af[i][1] = xs[(r0 + 8) * XS + kt * 8 + tig];
                af[i][2] = xs[r0 * XS + kt * 8 + tig + 4];
                af[i][3] = xs[(r0 + 8) * XS + kt * 8 + tig + 4];
            }
            #pragma unroll
            for (int j = 0; j < 4; j++) {
                int nc = (wc1 * 4 + j) * 8 + gid;
                bf[j][0] = rs[(kt * 8 + tig) * DP + nc];
                bf[j][1] = rs[(kt * 8 + tig + 4) * DP + nc];
            }
            #pragma unroll
            for (int i = 0; i < 2; i++)
                #pragma unroll
                for (int j = 0; j < 4; j++)
                    mma8(accT[i][j], af[i], bf[j]);
        }
    }

    // ---- store T (tf32) ----
    #pragma unroll
    for (int i = 0; i < 2; i++)
        #pragma unroll
        for (int j = 0; j < 4; j++) {
            int r0 = (wr1 * 2 + i) * 16 + gid;
            int nc = (wc1 * 4 + j) * 8 + 2 * tig;
            uint2 lo = make_uint2(f2tf(accT[i][j][0]), f2tf(accT[i][j][1]));
            uint2 hi = make_uint2(f2tf(accT[i][j][2]), f2tf(accT[i][j][3]));
            *(uint2*)&ts[r0 * DP + nc]       = lo;
            *(uint2*)&ts[(r0 + 8) * DP + nc] = hi;
        }
    __syncthreads();   // T visible; x chunk (lts alias) free to overwrite

    // ================= GEMM2 =================
    const int m   = w >> 2;           // 4 warps per m-row
    const int sw  = w & 3;
    const int wr2 = sw / WC2, wc2 = sw % WC2;
    float accY[2][4][4];
    #pragma unroll
    for (int i = 0; i < 2; i++)
        #pragma unroll
        for (int j = 0; j < 4; j++)
            #pragma unroll
            for (int q = 0; q < 4; q++) accY[i][j][q] = 0.0f;

    for (int ac = 0; ac < NC2; ac++) {
        if (ac) __syncthreads();   // protect lts overwrite vs previous mma reads
        // ---- LT chunk: [B][32 a], L transposed, /3, tf32, stride LTS ----
        #pragma unroll
        for (int i = tid; i < 32 * B; i += THREADS) {
            int acx = i / B, b = i % B;
            lts[b * LTS + acx] = f2tf(Lg[(ac * 32 + acx) * B + b] * (1.0f / 3.0f));
        }
        __syncthreads();

        #pragma unroll
        for (int kt = 0; kt < 4; kt++) {
            uint32_t af[2][4], bf[4][2];
            #pragma unroll
            for (int i = 0; i < 2; i++) {
                int rb = (wr2 * 2 + i) * 16 + gid;
                af[i][0] = lts[rb * LTS + kt * 8 + tig];
                af[i][1] = lts[(rb + 8) * LTS + kt * 8 + tig];
                af[i][2] = lts[rb * LTS + kt * 8 + tig + 4];
                af[i][3] = lts[(rb + 8) * LTS + kt * 8 + tig + 4];
            }
            #pragma unroll
            for (int j = 0; j < 4; j++) {
                int nc = (wc2 * 4 + j) * 8 + gid;
                bf[j][0] = ts[(m * A + ac * 32 + kt * 8 + tig) * DP + nc];
                bf[j][1] = ts[(m * A + ac * 32 + kt * 8 + tig + 4) * DP + nc];
            }
            #pragma unroll
            for (int i = 0; i < 2; i++)
                #pragma unroll
                for (int j = 0; j < 4; j++)
                    mma8(accY[i][j], af[i], bf[j]);
        }
    }

    // ---- RMW y (swizzled): ownership disjoint per thread within a factor ----
    #pragma unroll
    for (int i = 0; i < 2; i++)
        #pragma unroll
        for (int j = 0; j < 4; j++) {
            int b = (wr2 * 2 + i) * 16 + gid;
            int d = (wc2 * 4 + j) * 8 + 2 * tig;
            int n0 = b * D + d;
            int s0 = n0 + 2 * (n0 >> 5);
            float2 v0 = *(float2*)&ys[m * YS + s0];
            v0.x += accY[i][j][0]; v0.y += accY[i][j][1];
            *(float2*)&ys[m * YS + s0] = v0;
            int n2 = (b + 8) * D + d;
            int s2 = n2 + 2 * (n2 >> 5);
            float2 v2 = *(float2*)&ys[m * YS + s2];
            v2.x += accY[i][j][2]; v2.y += accY[i][j][3];
            *(float2*)&ys[m * YS + s2] = v2;
        }
}

__global__ __launch_bounds__(THREADS, 1) void klinear_kernel(
    const float* __restrict__ x,
    const float* __restrict__ L0, const float* __restrict__ R0,
    const float* __restrict__ L1, const float* __restrict__ R1,
    const float* __restrict__ L2, const float* __restrict__ R2,
    const float* __restrict__ bias,
    float* __restrict__ out)
{
    extern __shared__ float smem[];
    const int tid = threadIdx.x;
    const int m0  = blockIdx.x * MT;

    // zero y accumulator (bias added in epilogue)
    for (int i = tid; i < MT * YS; i += THREADS)
        smem[OFF_Y + i] = 0.0f;
    // (first factor's chunk-top __syncthreads orders this before any use)

    factor< 64,  64,  64,  64>(x, L0, R0, smem, m0, tid);
    factor< 32,  32, 128, 128>(x, L1, R1, smem, m0, tid);
    factor<128, 128,  32,  32>(x, L2, R2, smem, m0, tid);

    __syncthreads();

    // epilogue: y + bias -> out; thread owns n in [8*tid, 8*tid+8)
    const int n0 = tid * 8;
    const int s  = n0 + 2 * (n0 >> 5);   // contiguous within the 8-run
    float4 b0 = *(const float4*)&bias[n0];
    float4 b1 = *(const float4*)&bias[n0 + 4];
    #pragma unroll
    for (int m = 0; m < MT; m++) {
        const float* yr = smem + OFF_Y + m * YS + s;
        float2 p0 = *(const float2*)&yr[0];
        float2 p1 = *(const float2*)&yr[2];
        float2 p2 = *(const float2*)&yr[4];
        float2 p3 = *(const float2*)&yr[6];
        float4 o0 = make_float4(p0.x + b0.x, p0.y + b0.y, p1.x + b0.z, p1.y + b0.w);
        float4 o1 = make_float4(p2.x + b1.x, p2.y + b1.y, p3.x + b1.z, p3.y + b1.w);
        *(float4*)&out[(size_t)(m0 + m) * NF + n0]     = o0;
        *(float4*)&out[(size_t)(m0 + m) * NF + n0 + 4] = o1;
    }
}

extern "C" void kernel_launch(void* const* d_in, const int* in_sizes, int n_in,
                              void* d_out, int out_size)
{
    const float* x    = (const float*)d_in[0];
    const float* L0   = (const float*)d_in[1];
    const float* R0   = (const float*)d_in[2];
    const float* L1   = (const float*)d_in[3];
    const float* R1   = (const float*)d_in[4];
    const float* L2   = (const float*)d_in[5];
    const float* R2   = (const float*)d_in[6];
    const float* bias = (const float*)d_in[7];
    float* out = (float*)d_out;

    static bool attr_set = false;
    if (!attr_set) {
        cudaFuncSetAttribute(klinear_kernel,
                             cudaFuncAttributeMaxDynamicSharedMemorySize, SMEM_BYTES);
        attr_set = true;
    }

    klinear_kernel<<<16384 / MT, THREADS, SMEM_BYTES>>>(
        x, L0, R0, L1, R1, L2, R2, bias, out);
}